// round 1
// baseline (speedup 1.0000x reference)
#include <cuda_runtime.h>

// Problem constants
#define BSZ 4
#define CSZ 64
#define TSZ 1024
#define FSZ 128
#define HN  4
#define HIDN 4
#define CHN 16
#define NB  (HN*BSZ)      // 16 attention batches
#define DQK (HIDN*FSZ)    // 512
#define DV  (CHN*FSZ)     // 2048

// Scratch (device globals: allocation-free rule)
__device__ float g_q[(size_t)NB*TSZ*DQK];            // 33.5 MB
__device__ float g_k[(size_t)NB*TSZ*DQK];            // 33.5 MB
__device__ float g_v[(size_t)NB*TSZ*DV];             // 134 MB
__device__ float g_s[(size_t)NB*TSZ*TSZ];            // 67  MB
__device__ float g_ao[(size_t)BSZ*CSZ*TSZ*FSZ];      // 134 MB

// ---------------------------------------------------------------------------
// Kernel A: QKV head branches. One block per (b,t). x slice cached in smem.
// y = W·x + b -> PReLU -> ChannelNorm over (O,F) per head -> scale/shift
// ---------------------------------------------------------------------------
template<int O>
__device__ __forceinline__ void head_branch(
    const float* __restrict__ xs, float* ws, float* red,
    int b, int t, int tid,
    const float* __restrict__ W, const float* __restrict__ bias,
    const float* __restrict__ alpha, const float* __restrict__ g,
    const float* __restrict__ be, float* __restrict__ outb)
{
    constexpr int NW = HN*O*CSZ;
    constexpr int PT = HN*O*FSZ/256;     // outputs per thread
    constexpr int PERH = O/2;            // iterations per head (f-constant mapping)

    if (tid < 2*HN) red[tid] = 0.f;
    for (int i = tid; i < NW; i += 256) ws[i] = W[i];
    __syncthreads();

    const int f = tid & 127;
    const int ho0 = tid >> 7;   // 0 or 1; thread's (h,o) rows are ho0 + 2*it

    float acc[PT];
    #pragma unroll
    for (int it = 0; it < PT; it++) acc[it] = bias[ho0 + 2*it];

    #pragma unroll
    for (int cb = 0; cb < CSZ; cb += 16) {
        float xr[16];
        #pragma unroll
        for (int cc = 0; cc < 16; cc++) xr[cc] = xs[(cb+cc)*FSZ + f];
        #pragma unroll
        for (int it = 0; it < PT; it++) {
            const float* wr = ws + (ho0 + 2*it)*CSZ + cb;
            #pragma unroll
            for (int cc = 0; cc < 16; cc++) acc[it] += xr[cc]*wr[cc];
        }
    }

    float al[HN];
    #pragma unroll
    for (int h = 0; h < HN; h++) al[h] = alpha[h];

    float s1[HN], s2[HN];
    #pragma unroll
    for (int h = 0; h < HN; h++) { s1[h] = 0.f; s2[h] = 0.f; }

    #pragma unroll
    for (int it = 0; it < PT; it++) {
        const int h = it / PERH;   // compile-time per unrolled it
        float y = acc[it];
        y = y > 0.f ? y : al[h]*y;
        acc[it] = y;
        s1[h] += y; s2[h] += y*y;
    }
    // warp prereduce then atomics
    #pragma unroll
    for (int h = 0; h < HN; h++) {
        float a1 = s1[h], a2 = s2[h];
        #pragma unroll
        for (int off = 16; off; off >>= 1) {
            a1 += __shfl_xor_sync(0xffffffffu, a1, off);
            a2 += __shfl_xor_sync(0xffffffffu, a2, off);
        }
        if ((tid & 31) == 0) { atomicAdd(&red[h], a1); atomicAdd(&red[HN+h], a2); }
    }
    __syncthreads();

    constexpr float invn = 1.0f/(O*FSZ);
    float mean[HN], rstd[HN];
    #pragma unroll
    for (int h = 0; h < HN; h++) {
        mean[h] = red[h]*invn;
        float var = red[HN+h]*invn - mean[h]*mean[h];
        rstd[h] = rsqrtf(var + 1e-5f);
    }
    #pragma unroll
    for (int it = 0; it < PT; it++) {
        const int ho = ho0 + 2*it;
        const int h = it / PERH;
        const int o = ho - h*O;
        const int j = ho*FSZ + f;
        const int n = h*BSZ + b;
        float val = (acc[it]-mean[h])*rstd[h]*g[j] + be[j];
        outb[((size_t)n*TSZ + t)*(O*FSZ) + o*FSZ + f] = val;
    }
    __syncthreads();
}

__global__ void __launch_bounds__(256) qkv_kernel(
    const float* __restrict__ x,
    const float* Wq, const float* bq, const float* aq, const float* gq, const float* beq,
    const float* Wk, const float* bk, const float* ak, const float* gk, const float* bek,
    const float* Wv, const float* bv, const float* av, const float* gv, const float* bev)
{
    extern __shared__ float sm[];
    float* xs = sm;           // 8192 floats: x[b,:,t,:]
    float* ws = sm + 8192;    // up to 4096 floats: weights
    __shared__ float red[2*HN];
    const int tid = threadIdx.x;
    const int b = blockIdx.x >> 10, t = blockIdx.x & 1023;

    for (int i = tid; i < CSZ*FSZ; i += 256) {
        int c = i >> 7, f = i & 127;
        xs[i] = x[(((size_t)b*CSZ + c)*TSZ + t)*FSZ + f];
    }
    __syncthreads();

    head_branch<HIDN>(xs, ws, red, b, t, tid, Wq, bq, aq, gq, beq, g_q);
    head_branch<HIDN>(xs, ws, red, b, t, tid, Wk, bk, ak, gk, bek, g_k);
    head_branch<CHN >(xs, ws, red, b, t, tid, Wv, bv, av, gv, bev, g_v);
}

// ---------------------------------------------------------------------------
// Kernel B: S = scale * Q K^T   (batched NT GEMM, 128x128x8, 8x8/thread)
// ---------------------------------------------------------------------------
__global__ void __launch_bounds__(256) gemm_qk_kernel()
{
    __shared__ float As[8][132];
    __shared__ float Bs[8][132];
    const int n = blockIdx.z;
    const float* A  = g_q + (size_t)n*TSZ*DQK;
    const float* Bp = g_k + (size_t)n*TSZ*DQK;
    float* Cp = g_s + (size_t)n*TSZ*TSZ;
    const int m0 = blockIdx.y*128, n0 = blockIdx.x*128;
    const int tid = threadIdx.x;
    const int lrow = tid >> 1, lc4 = (tid & 1)*4;
    const int tx = tid & 15, ty = tid >> 4;

    float acc[8][8];
    #pragma unroll
    for (int i = 0; i < 8; i++)
        #pragma unroll
        for (int j = 0; j < 8; j++) acc[i][j] = 0.f;

    for (int k0 = 0; k0 < DQK; k0 += 8) {
        float4 va = *(const float4*)(A  + (size_t)(m0+lrow)*DQK + k0 + lc4);
        float4 vb = *(const float4*)(Bp + (size_t)(n0+lrow)*DQK + k0 + lc4);
        __syncthreads();
        As[lc4+0][lrow]=va.x; As[lc4+1][lrow]=va.y; As[lc4+2][lrow]=va.z; As[lc4+3][lrow]=va.w;
        Bs[lc4+0][lrow]=vb.x; Bs[lc4+1][lrow]=vb.y; Bs[lc4+2][lrow]=vb.z; Bs[lc4+3][lrow]=vb.w;
        __syncthreads();
        #pragma unroll
        for (int kk = 0; kk < 8; kk++) {
            float4 t0 = *(const float4*)&As[kk][ty*4];
            float4 t1 = *(const float4*)&As[kk][64+ty*4];
            float4 u0 = *(const float4*)&Bs[kk][tx*4];
            float4 u1 = *(const float4*)&Bs[kk][64+tx*4];
            float a_[8] = {t0.x,t0.y,t0.z,t0.w,t1.x,t1.y,t1.z,t1.w};
            float b_[8] = {u0.x,u0.y,u0.z,u0.w,u1.x,u1.y,u1.z,u1.w};
            #pragma unroll
            for (int i = 0; i < 8; i++)
                #pragma unroll
                for (int j = 0; j < 8; j++) acc[i][j] += a_[i]*b_[j];
        }
    }
    const float scale = 0.0441941738241592f;  // 1/sqrt(512)
    #pragma unroll
    for (int i = 0; i < 8; i++) {
        int r = m0 + (i < 4 ? ty*4+i : 64 + ty*4 + (i-4));
        float* crow = Cp + (size_t)r*TSZ;
        float4 o0 = make_float4(acc[i][0]*scale, acc[i][1]*scale, acc[i][2]*scale, acc[i][3]*scale);
        float4 o1 = make_float4(acc[i][4]*scale, acc[i][5]*scale, acc[i][6]*scale, acc[i][7]*scale);
        *(float4*)(crow + n0 + tx*4)      = o0;
        *(float4*)(crow + n0 + 64 + tx*4) = o1;
    }
}

// ---------------------------------------------------------------------------
// Kernel C: row softmax over g_s (16384 rows of 1024)
// ---------------------------------------------------------------------------
__global__ void __launch_bounds__(256) softmax_kernel()
{
    float* p = g_s + (size_t)blockIdx.x*TSZ;
    const int tid = threadIdx.x;
    __shared__ float red[256];

    float v0 = p[tid], v1 = p[tid+256], v2 = p[tid+512], v3 = p[tid+768];
    float m = fmaxf(fmaxf(v0,v1), fmaxf(v2,v3));
    red[tid] = m; __syncthreads();
    #pragma unroll
    for (int s = 128; s > 0; s >>= 1) {
        if (tid < s) red[tid] = fmaxf(red[tid], red[tid+s]);
        __syncthreads();
    }
    m = red[0]; __syncthreads();

    v0 = __expf(v0-m); v1 = __expf(v1-m); v2 = __expf(v2-m); v3 = __expf(v3-m);
    red[tid] = v0+v1+v2+v3; __syncthreads();
    #pragma unroll
    for (int s = 128; s > 0; s >>= 1) {
        if (tid < s) red[tid] += red[tid+s];
        __syncthreads();
    }
    float inv = 1.0f/red[0];
    p[tid] = v0*inv; p[tid+256] = v1*inv; p[tid+512] = v2*inv; p[tid+768] = v3*inv;
}

// ---------------------------------------------------------------------------
// Kernel D: O = P V (batched NN GEMM), writing directly into (B,C,T,F) layout
// ---------------------------------------------------------------------------
__global__ void __launch_bounds__(256) gemm_pv_kernel()
{
    __shared__ float As[8][132];
    __shared__ float Bs[8][132];
    const int n = blockIdx.z;
    const float* A  = g_s + (size_t)n*TSZ*TSZ;
    const float* Bp = g_v + (size_t)n*TSZ*DV;
    const int m0 = blockIdx.y*128, n0 = blockIdx.x*128;
    const int tid = threadIdx.x;
    const int lrow = tid >> 1, lc4 = (tid & 1)*4;   // A (transpose-load)
    const int krow = tid >> 5, bc  = (tid & 31)*4;  // B (direct-load)
    const int tx = tid & 15, ty = tid >> 4;

    float acc[8][8];
    #pragma unroll
    for (int i = 0; i < 8; i++)
        #pragma unroll
        for (int j = 0; j < 8; j++) acc[i][j] = 0.f;

    for (int k0 = 0; k0 < TSZ; k0 += 8) {
        float4 va = *(const float4*)(A  + (size_t)(m0+lrow)*TSZ + k0 + lc4);
        float4 vb = *(const float4*)(Bp + (size_t)(k0+krow)*DV + n0 + bc);
        __syncthreads();
        As[lc4+0][lrow]=va.x; As[lc4+1][lrow]=va.y; As[lc4+2][lrow]=va.z; As[lc4+3][lrow]=va.w;
        *(float4*)&Bs[krow][bc] = vb;
        __syncthreads();
        #pragma unroll
        for (int kk = 0; kk < 8; kk++) {
            float4 t0 = *(const float4*)&As[kk][ty*4];
            float4 t1 = *(const float4*)&As[kk][64+ty*4];
            float4 u0 = *(const float4*)&Bs[kk][tx*4];
            float4 u1 = *(const float4*)&Bs[kk][64+tx*4];
            float a_[8] = {t0.x,t0.y,t0.z,t0.w,t1.x,t1.y,t1.z,t1.w};
            float b_[8] = {u0.x,u0.y,u0.z,u0.w,u1.x,u1.y,u1.z,u1.w};
            #pragma unroll
            for (int i = 0; i < 8; i++)
                #pragma unroll
                for (int j = 0; j < 8; j++) acc[i][j] += a_[i]*b_[j];
        }
    }
    // write into (B,C,T,F): n=h*B+b, d=ch*F+f -> c=h*CH+ch
    const int h = n >> 2, bb = n & 3;
    #pragma unroll
    for (int i = 0; i < 8; i++) {
        int r = m0 + (i < 4 ? ty*4+i : 64 + ty*4 + (i-4));
        #pragma unroll
        for (int jb = 0; jb < 2; jb++) {
            int nc = n0 + jb*64 + tx*4;
            int ch = nc >> 7, f = nc & 127;
            int c = h*CHN + ch;
            float4 o = make_float4(acc[i][jb*4+0], acc[i][jb*4+1], acc[i][jb*4+2], acc[i][jb*4+3]);
            *(float4*)(g_ao + (((size_t)(bb*CSZ + c)*TSZ + r)*FSZ + f)) = o;
        }
    }
}

// ---------------------------------------------------------------------------
// Kernel E: projection + PReLU + norm over (C,F) + gp/betap + residual
// ---------------------------------------------------------------------------
__global__ void __launch_bounds__(256) proj_kernel(
    const float* __restrict__ x, const float* __restrict__ Wp,
    const float* __restrict__ bp, const float* __restrict__ ap,
    const float* __restrict__ gp, const float* __restrict__ bep,
    float* __restrict__ out)
{
    extern __shared__ float sm[];
    float* xs = sm;          // 8192: ao[b,:,t,:]
    float* ws = sm + 8192;   // 4096: Wp
    __shared__ float red[2];
    const int tid = threadIdx.x;
    const int b = blockIdx.x >> 10, t = blockIdx.x & 1023;

    for (int i = tid; i < CSZ*FSZ; i += 256) {
        int c = i >> 7, f = i & 127;
        xs[i] = g_ao[(((size_t)b*CSZ + c)*TSZ + t)*FSZ + f];
    }
    for (int i = tid; i < CSZ*CSZ; i += 256) ws[i] = Wp[i];
    if (tid < 2) red[tid] = 0.f;
    __syncthreads();

    const int f = tid & 127;
    const int o0 = tid >> 7;
    constexpr int PT = 32;   // 64*128/256
    float acc[PT];
    #pragma unroll
    for (int it = 0; it < PT; it++) acc[it] = bp[o0 + 2*it];

    #pragma unroll
    for (int cb = 0; cb < CSZ; cb += 16) {
        float xr[16];
        #pragma unroll
        for (int cc = 0; cc < 16; cc++) xr[cc] = xs[(cb+cc)*FSZ + f];
        #pragma unroll
        for (int it = 0; it < PT; it++) {
            const float* wr = ws + (o0 + 2*it)*CSZ + cb;
            #pragma unroll
            for (int cc = 0; cc < 16; cc++) acc[it] += xr[cc]*wr[cc];
        }
    }

    const float a = ap[0];
    float s1 = 0.f, s2 = 0.f;
    #pragma unroll
    for (int it = 0; it < PT; it++) {
        float y = acc[it];
        y = y > 0.f ? y : a*y;
        acc[it] = y; s1 += y; s2 += y*y;
    }
    #pragma unroll
    for (int off = 16; off; off >>= 1) {
        s1 += __shfl_xor_sync(0xffffffffu, s1, off);
        s2 += __shfl_xor_sync(0xffffffffu, s2, off);
    }
    if ((tid & 31) == 0) { atomicAdd(&red[0], s1); atomicAdd(&red[1], s2); }
    __syncthreads();

    constexpr float invn = 1.0f/(CSZ*FSZ);
    float mean = red[0]*invn;
    float var = red[1]*invn - mean*mean;
    float rstd = rsqrtf(var + 1e-5f);
    #pragma unroll
    for (int it = 0; it < PT; it++) {
        int o = o0 + 2*it;
        int j = o*FSZ + f;
        size_t gi = (((size_t)b*CSZ + o)*TSZ + t)*FSZ + f;
        out[gi] = (acc[it]-mean)*rstd*gp[j] + bep[j] + x[gi];
    }
}

// ---------------------------------------------------------------------------
extern "C" void kernel_launch(void* const* d_in, const int* in_sizes, int n_in,
                              void* d_out, int out_size)
{
    const float* x   = (const float*)d_in[0];
    const float* Wq  = (const float*)d_in[1];
    const float* bq  = (const float*)d_in[2];
    const float* aq  = (const float*)d_in[3];
    const float* gq  = (const float*)d_in[4];
    const float* beq = (const float*)d_in[5];
    const float* Wk  = (const float*)d_in[6];
    const float* bk  = (const float*)d_in[7];
    const float* ak  = (const float*)d_in[8];
    const float* gk  = (const float*)d_in[9];
    const float* bek = (const float*)d_in[10];
    const float* Wv  = (const float*)d_in[11];
    const float* bv  = (const float*)d_in[12];
    const float* av  = (const float*)d_in[13];
    const float* gv  = (const float*)d_in[14];
    const float* bev = (const float*)d_in[15];
    const float* Wp  = (const float*)d_in[16];
    const float* bp  = (const float*)d_in[17];
    const float* ap  = (const float*)d_in[18];
    const float* gp  = (const float*)d_in[19];
    const float* bep = (const float*)d_in[20];
    float* out = (float*)d_out;

    const int SMEM = 12288*(int)sizeof(float);   // 48 KB dynamic
    cudaFuncSetAttribute(qkv_kernel,  cudaFuncAttributeMaxDynamicSharedMemorySize, SMEM);
    cudaFuncSetAttribute(proj_kernel, cudaFuncAttributeMaxDynamicSharedMemorySize, SMEM);

    qkv_kernel<<<BSZ*TSZ, 256, SMEM>>>(x, Wq, bq, aq, gq, beq,
                                       Wk, bk, ak, gk, bek,
                                       Wv, bv, av, gv, bev);
    gemm_qk_kernel<<<dim3(8, 8, NB), 256>>>();
    softmax_kernel<<<NB*TSZ, 256>>>();
    gemm_pv_kernel<<<dim3(16, 8, NB), 256>>>();
    proj_kernel<<<BSZ*TSZ, 256, SMEM>>>(x, Wp, bp, ap, gp, bep, out);
}

// round 3
// speedup vs baseline: 1.6495x; 1.6495x over previous
#include <cuda_runtime.h>
#include <cstdint>

// Problem constants
#define BSZ 4
#define CSZ 64
#define TSZ 1024
#define FSZ 128
#define HN  4
#define HIDN 4
#define CHN 16
#define NB  (HN*BSZ)      // 16 attention batches
#define DQK (HIDN*FSZ)    // 512
#define DV  (CHN*FSZ)     // 2048

// Scratch (device globals: allocation-free rule)
__device__ float g_q [(size_t)NB*TSZ*DQK];           // [n][t][d]
__device__ float g_k [(size_t)NB*TSZ*DQK];           // [n][t][d]
__device__ float g_v [(size_t)NB*TSZ*DV];            // [n][t][d]
__device__ float g_vt[(size_t)NB*DV*TSZ];            // [n][d][t]
__device__ float g_s [(size_t)NB*TSZ*TSZ];           // [n][t][t']
__device__ float g_ao[(size_t)BSZ*CSZ*TSZ*FSZ];

// ===========================================================================
// mma.sync helpers (portable PTX, works on compute_103 target)
// ===========================================================================
__device__ __forceinline__ uint32_t smem_u32(const void* p) {
    uint32_t a;
    asm("{ .reg .u64 t; cvta.to.shared.u64 t, %1; cvt.u32.u64 %0, t; }" : "=r"(a) : "l"(p));
    return a;
}
__device__ __forceinline__ uint32_t cvt_tf32(float v) {
    uint32_t r;
    asm("cvt.rna.tf32.f32 %0, %1;" : "=r"(r) : "f"(v));
    return r;
}
__device__ __forceinline__ void ldsm4(uint32_t& r0, uint32_t& r1, uint32_t& r2, uint32_t& r3,
                                      uint32_t addr) {
    asm volatile("ldmatrix.sync.aligned.m8n8.x4.shared.b16 {%0,%1,%2,%3}, [%4];"
                 : "=r"(r0), "=r"(r1), "=r"(r2), "=r"(r3) : "r"(addr));
}
__device__ __forceinline__ void mma8(float* d, const uint32_t* a, uint32_t b0, uint32_t b1) {
    asm volatile("mma.sync.aligned.m16n8k8.row.col.f32.tf32.tf32.f32 "
                 "{%0,%1,%2,%3}, {%4,%5,%6,%7}, {%8,%9}, {%0,%1,%2,%3};"
                 : "+f"(d[0]), "+f"(d[1]), "+f"(d[2]), "+f"(d[3])
                 : "r"(a[0]), "r"(a[1]), "r"(a[2]), "r"(a[3]), "r"(b0), "r"(b1));
}

#define LDS_ROW 36              // 32 k-floats + 4 pad (conflict-free ldmatrix)
#define TILE_U32 (128*LDS_ROW)  // one 128x32 tile in smem (u32 units)

// ===========================================================================
// GEMM 1: S = scale * Q K^T   (3xTF32 split, NT, 128x128x32 tiles)
// ===========================================================================
__global__ void __launch_bounds__(256, 2) gemm_qk_mma()
{
    extern __shared__ uint32_t smq[];
    uint32_t* Ah = smq;
    uint32_t* Al = smq + TILE_U32;
    uint32_t* Bh = smq + 2*TILE_U32;
    uint32_t* Bl = smq + 3*TILE_U32;

    const int tid = threadIdx.x, lane = tid & 31, warp = tid >> 5;
    const int wm = warp >> 2, wn = warp & 3;          // 2 x 4 warp grid
    const int bz = blockIdx.z, m0 = blockIdx.y*128, n0 = blockIdx.x*128;
    const float* A = g_q + ((size_t)bz*TSZ + m0)*DQK;
    const float* B = g_k + ((size_t)bz*TSZ + n0)*DQK;

    float acc[4][4][4];
    #pragma unroll
    for (int i = 0; i < 4; i++)
        #pragma unroll
        for (int j = 0; j < 4; j++)
            #pragma unroll
            for (int k = 0; k < 4; k++) acc[i][j][k] = 0.f;

    // ldmatrix per-thread base addresses (byte)
    const uint32_t sbase = smem_u32(smq);
    const uint32_t pAh = sbase + (((wm*64 + (lane & 15))*LDS_ROW) + (lane >> 4)*4)*4;
    const uint32_t pAl = pAh + TILE_U32*4;
    const uint32_t pBh = sbase + (2*TILE_U32 + (wn*32 + lane)*LDS_ROW)*4;
    const uint32_t pBl = pBh + TILE_U32*4;

    for (int c = 0; c < DQK/32; c++) {
        float4 va[4], vb[4];
        #pragma unroll
        for (int j = 0; j < 4; j++) {
            int idx = tid + 256*j, rr = idx >> 3, qq = idx & 7;
            va[j] = *(const float4*)(A + (size_t)rr*DQK + c*32 + qq*4);
            vb[j] = *(const float4*)(B + (size_t)rr*DQK + c*32 + qq*4);
        }
        __syncthreads();
        #pragma unroll
        for (int j = 0; j < 4; j++) {
            int idx = tid + 256*j, rr = idx >> 3, qq = idx & 7;
            int o = rr*LDS_ROW + qq*4;
            uint4 h, l;
            h.x = cvt_tf32(va[j].x); l.x = cvt_tf32(va[j].x - __uint_as_float(h.x));
            h.y = cvt_tf32(va[j].y); l.y = cvt_tf32(va[j].y - __uint_as_float(h.y));
            h.z = cvt_tf32(va[j].z); l.z = cvt_tf32(va[j].z - __uint_as_float(h.z));
            h.w = cvt_tf32(va[j].w); l.w = cvt_tf32(va[j].w - __uint_as_float(h.w));
            *(uint4*)(Ah + o) = h; *(uint4*)(Al + o) = l;
            h.x = cvt_tf32(vb[j].x); l.x = cvt_tf32(vb[j].x - __uint_as_float(h.x));
            h.y = cvt_tf32(vb[j].y); l.y = cvt_tf32(vb[j].y - __uint_as_float(h.y));
            h.z = cvt_tf32(vb[j].z); l.z = cvt_tf32(vb[j].z - __uint_as_float(h.z));
            h.w = cvt_tf32(vb[j].w); l.w = cvt_tf32(vb[j].w - __uint_as_float(h.w));
            *(uint4*)(Bh + o) = h; *(uint4*)(Bl + o) = l;
        }
        __syncthreads();

        #pragma unroll
        for (int ks = 0; ks < 4; ks++) {
            uint32_t ah[4][4], al[4][4], bh0[4], bh1[4], bl0[4], bl1[4];
            #pragma unroll
            for (int im = 0; im < 4; im++) {
                ldsm4(ah[im][0], ah[im][1], ah[im][2], ah[im][3], pAh + im*(16*LDS_ROW*4) + ks*32);
                ldsm4(al[im][0], al[im][1], al[im][2], al[im][3], pAl + im*(16*LDS_ROW*4) + ks*32);
            }
            ldsm4(bh0[0], bh0[1], bh0[2], bh0[3], pBh + ks*32);
            ldsm4(bh1[0], bh1[1], bh1[2], bh1[3], pBh + ks*32 + 16);
            ldsm4(bl0[0], bl0[1], bl0[2], bl0[3], pBl + ks*32);
            ldsm4(bl1[0], bl1[1], bl1[2], bl1[3], pBl + ks*32 + 16);
            #pragma unroll
            for (int im = 0; im < 4; im++)
                #pragma unroll
                for (int in = 0; in < 4; in++) {
                    mma8(acc[im][in], ah[im], bh0[in], bh1[in]);
                    mma8(acc[im][in], ah[im], bl0[in], bl1[in]);
                    mma8(acc[im][in], al[im], bh0[in], bh1[in]);
                }
        }
    }

    // epilogue: scale + store
    const float scale = 0.0441941738241592f;   // 1/sqrt(512)
    float* Cb = g_s + (size_t)bz*TSZ*TSZ;
    const int mbase = m0 + wm*64, nbase = n0 + wn*32;
    #pragma unroll
    for (int im = 0; im < 4; im++)
        #pragma unroll
        for (int in = 0; in < 4; in++) {
            int rr = mbase + im*16 + (lane >> 2);
            int cc = nbase + in*8 + (lane & 3)*2;
            float2 o0 = make_float2(acc[im][in][0]*scale, acc[im][in][1]*scale);
            float2 o1 = make_float2(acc[im][in][2]*scale, acc[im][in][3]*scale);
            *(float2*)(Cb + (size_t)rr*TSZ + cc)     = o0;
            *(float2*)(Cb + (size_t)(rr+8)*TSZ + cc) = o1;
        }
}

// ===========================================================================
// GEMM 2: O = P V   (single-pass TF32, NT via V^T, 128x128x32 tiles)
// ===========================================================================
__global__ void __launch_bounds__(256, 2) gemm_pv_mma()
{
    extern __shared__ uint32_t smp[];
    uint32_t* As = smp;
    uint32_t* Bs = smp + TILE_U32;

    const int tid = threadIdx.x, lane = tid & 31, warp = tid >> 5;
    const int wm = warp >> 2, wn = warp & 3;
    const int bz = blockIdx.z, m0 = blockIdx.y*128, n0 = blockIdx.x*128;
    const float* A = g_s  + (size_t)bz*TSZ*TSZ + (size_t)m0*TSZ;
    const float* B = g_vt + ((size_t)bz*DV + n0)*TSZ;

    float acc[4][4][4];
    #pragma unroll
    for (int i = 0; i < 4; i++)
        #pragma unroll
        for (int j = 0; j < 4; j++)
            #pragma unroll
            for (int k = 0; k < 4; k++) acc[i][j][k] = 0.f;

    const uint32_t sbase = smem_u32(smp);
    const uint32_t pA = sbase + (((wm*64 + (lane & 15))*LDS_ROW) + (lane >> 4)*4)*4;
    const uint32_t pB = sbase + (TILE_U32 + (wn*32 + lane)*LDS_ROW)*4;

    for (int c = 0; c < TSZ/32; c++) {
        float4 va[4], vb[4];
        #pragma unroll
        for (int j = 0; j < 4; j++) {
            int idx = tid + 256*j, rr = idx >> 3, qq = idx & 7;
            va[j] = *(const float4*)(A + (size_t)rr*TSZ + c*32 + qq*4);
            vb[j] = *(const float4*)(B + (size_t)rr*TSZ + c*32 + qq*4);
        }
        __syncthreads();
        #pragma unroll
        for (int j = 0; j < 4; j++) {
            int idx = tid + 256*j, rr = idx >> 3, qq = idx & 7;
            int o = rr*LDS_ROW + qq*4;
            uint4 h;
            h.x = cvt_tf32(va[j].x); h.y = cvt_tf32(va[j].y);
            h.z = cvt_tf32(va[j].z); h.w = cvt_tf32(va[j].w);
            *(uint4*)(As + o) = h;
            h.x = cvt_tf32(vb[j].x); h.y = cvt_tf32(vb[j].y);
            h.z = cvt_tf32(vb[j].z); h.w = cvt_tf32(vb[j].w);
            *(uint4*)(Bs + o) = h;
        }
        __syncthreads();

        #pragma unroll
        for (int ks = 0; ks < 4; ks++) {
            uint32_t a[4][4], b0[4], b1[4];
            #pragma unroll
            for (int im = 0; im < 4; im++)
                ldsm4(a[im][0], a[im][1], a[im][2], a[im][3], pA + im*(16*LDS_ROW*4) + ks*32);
            ldsm4(b0[0], b0[1], b0[2], b0[3], pB + ks*32);
            ldsm4(b1[0], b1[1], b1[2], b1[3], pB + ks*32 + 16);
            #pragma unroll
            for (int im = 0; im < 4; im++)
                #pragma unroll
                for (int in = 0; in < 4; in++)
                    mma8(acc[im][in], a[im], b0[in], b1[in]);
        }
    }

    // epilogue: write into (B,C,T,F). DV tile index == ch (F=128 per tile)
    const int h = bz >> 2, bb = bz & 3;
    const int cc_ch = h*CHN + blockIdx.x;
    const int mbase = m0 + wm*64, nbase = wn*32;
    float* Ob = g_ao + ((size_t)(bb*CSZ + cc_ch)*TSZ)*FSZ;
    #pragma unroll
    for (int im = 0; im < 4; im++)
        #pragma unroll
        for (int in = 0; in < 4; in++) {
            int rr = mbase + im*16 + (lane >> 2);
            int ff = nbase + in*8 + (lane & 3)*2;
            float2 o0 = make_float2(acc[im][in][0], acc[im][in][1]);
            float2 o1 = make_float2(acc[im][in][2], acc[im][in][3]);
            *(float2*)(Ob + (size_t)rr*FSZ + ff)     = o0;
            *(float2*)(Ob + (size_t)(rr+8)*FSZ + ff) = o1;
        }
}

// ===========================================================================
// V transpose: g_v [n][t][d] -> g_vt [n][d][t] (smem-tiled, coalesced)
// ===========================================================================
__global__ void __launch_bounds__(256) vtrans_kernel()
{
    __shared__ float ts[32][33];
    const int n = blockIdx.z;
    const int d0 = blockIdx.x*32, t0 = blockIdx.y*32;
    const int tx = threadIdx.x & 31, ty = threadIdx.x >> 5;   // ty 0..7
    const float* src = g_v + (size_t)n*TSZ*DV;
    #pragma unroll
    for (int k = 0; k < 4; k++)
        ts[ty + 8*k][tx] = src[(size_t)(t0 + ty + 8*k)*DV + d0 + tx];
    __syncthreads();
    float* dst = g_vt + (size_t)n*DV*TSZ;
    #pragma unroll
    for (int k = 0; k < 4; k++)
        dst[(size_t)(d0 + ty + 8*k)*TSZ + t0 + tx] = ts[tx][ty + 8*k];
}

// ===========================================================================
// Kernel A: QKV head branches (round-1 proven version; V written normally)
// ===========================================================================
template<int O>
__device__ __forceinline__ void head_branch(
    const float* __restrict__ xs, float* ws, float* red,
    int b, int t, int tid,
    const float* __restrict__ W, const float* __restrict__ bias,
    const float* __restrict__ alpha, const float* __restrict__ g,
    const float* __restrict__ be, float* __restrict__ outb)
{
    constexpr int NW = HN*O*CSZ;
    constexpr int PT = HN*O*FSZ/256;
    constexpr int PERH = O/2;

    if (tid < 2*HN) red[tid] = 0.f;
    for (int i = tid; i < NW; i += 256) ws[i] = W[i];
    __syncthreads();

    const int f = tid & 127;
    const int ho0 = tid >> 7;

    float acc[PT];
    #pragma unroll
    for (int it = 0; it < PT; it++) acc[it] = bias[ho0 + 2*it];

    #pragma unroll
    for (int cb = 0; cb < CSZ; cb += 16) {
        float xr[16];
        #pragma unroll
        for (int cc = 0; cc < 16; cc++) xr[cc] = xs[(cb+cc)*FSZ + f];
        #pragma unroll
        for (int it = 0; it < PT; it++) {
            const float* wr = ws + (ho0 + 2*it)*CSZ + cb;
            #pragma unroll
            for (int cc = 0; cc < 16; cc++) acc[it] += xr[cc]*wr[cc];
        }
    }

    float al[HN];
    #pragma unroll
    for (int h = 0; h < HN; h++) al[h] = alpha[h];

    float s1[HN], s2[HN];
    #pragma unroll
    for (int h = 0; h < HN; h++) { s1[h] = 0.f; s2[h] = 0.f; }

    #pragma unroll
    for (int it = 0; it < PT; it++) {
        const int h = it / PERH;
        float y = acc[it];
        y = y > 0.f ? y : al[h]*y;
        acc[it] = y;
        s1[h] += y; s2[h] += y*y;
    }
    #pragma unroll
    for (int h = 0; h < HN; h++) {
        float a1 = s1[h], a2 = s2[h];
        #pragma unroll
        for (int off = 16; off; off >>= 1) {
            a1 += __shfl_xor_sync(0xffffffffu, a1, off);
            a2 += __shfl_xor_sync(0xffffffffu, a2, off);
        }
        if ((tid & 31) == 0) { atomicAdd(&red[h], a1); atomicAdd(&red[HN+h], a2); }
    }
    __syncthreads();

    constexpr float invn = 1.0f/(O*FSZ);
    float mean[HN], rstd[HN];
    #pragma unroll
    for (int h = 0; h < HN; h++) {
        mean[h] = red[h]*invn;
        float var = red[HN+h]*invn - mean[h]*mean[h];
        rstd[h] = rsqrtf(var + 1e-5f);
    }
    #pragma unroll
    for (int it = 0; it < PT; it++) {
        const int ho = ho0 + 2*it;
        const int h = it / PERH;
        const int o = ho - h*O;
        const int j = ho*FSZ + f;
        const int n = h*BSZ + b;
        float val = (acc[it]-mean[h])*rstd[h]*g[j] + be[j];
        outb[((size_t)n*TSZ + t)*(O*FSZ) + o*FSZ + f] = val;
    }
    __syncthreads();
}

__global__ void __launch_bounds__(256) qkv_kernel(
    const float* __restrict__ x,
    const float* Wq, const float* bq, const float* aq, const float* gq, const float* beq,
    const float* Wk, const float* bk, const float* ak, const float* gk, const float* bek,
    const float* Wv, const float* bv, const float* av, const float* gv, const float* bev)
{
    extern __shared__ float sm[];
    float* xs = sm;
    float* ws = sm + 8192;
    __shared__ float red[2*HN];
    const int tid = threadIdx.x;
    const int b = blockIdx.x >> 10, t = blockIdx.x & 1023;

    for (int i = tid; i < CSZ*FSZ; i += 256) {
        int c = i >> 7, f = i & 127;
        xs[i] = x[(((size_t)b*CSZ + c)*TSZ + t)*FSZ + f];
    }
    __syncthreads();

    head_branch<HIDN>(xs, ws, red, b, t, tid, Wq, bq, aq, gq, beq, g_q);
    head_branch<HIDN>(xs, ws, red, b, t, tid, Wk, bk, ak, gk, bek, g_k);
    head_branch<CHN >(xs, ws, red, b, t, tid, Wv, bv, av, gv, bev, g_v);
}

// ===========================================================================
// Kernel C: row softmax over g_s (16384 rows of 1024)
// ===========================================================================
__global__ void __launch_bounds__(256) softmax_kernel()
{
    float* p = g_s + (size_t)blockIdx.x*TSZ;
    const int tid = threadIdx.x;
    __shared__ float red[256];

    float v0 = p[tid], v1 = p[tid+256], v2 = p[tid+512], v3 = p[tid+768];
    float m = fmaxf(fmaxf(v0,v1), fmaxf(v2,v3));
    red[tid] = m; __syncthreads();
    #pragma unroll
    for (int s = 128; s > 0; s >>= 1) {
        if (tid < s) red[tid] = fmaxf(red[tid], red[tid+s]);
        __syncthreads();
    }
    m = red[0]; __syncthreads();

    v0 = __expf(v0-m); v1 = __expf(v1-m); v2 = __expf(v2-m); v3 = __expf(v3-m);
    red[tid] = v0+v1+v2+v3; __syncthreads();
    #pragma unroll
    for (int s = 128; s > 0; s >>= 1) {
        if (tid < s) red[tid] += red[tid+s];
        __syncthreads();
    }
    float inv = 1.0f/red[0];
    p[tid] = v0*inv; p[tid+256] = v1*inv; p[tid+512] = v2*inv; p[tid+768] = v3*inv;
}

// ===========================================================================
// Kernel E: projection + PReLU + norm + residual
// ===========================================================================
__global__ void __launch_bounds__(256) proj_kernel(
    const float* __restrict__ x, const float* __restrict__ Wp,
    const float* __restrict__ bp, const float* __restrict__ ap,
    const float* __restrict__ gp, const float* __restrict__ bep,
    float* __restrict__ out)
{
    extern __shared__ float sm[];
    float* xs = sm;
    float* ws = sm + 8192;
    __shared__ float red[2];
    const int tid = threadIdx.x;
    const int b = blockIdx.x >> 10, t = blockIdx.x & 1023;

    for (int i = tid; i < CSZ*FSZ; i += 256) {
        int c = i >> 7, f = i & 127;
        xs[i] = g_ao[(((size_t)b*CSZ + c)*TSZ + t)*FSZ + f];
    }
    for (int i = tid; i < CSZ*CSZ; i += 256) ws[i] = Wp[i];
    if (tid < 2) red[tid] = 0.f;
    __syncthreads();

    const int f = tid & 127;
    const int o0 = tid >> 7;
    constexpr int PT = 32;
    float acc[PT];
    #pragma unroll
    for (int it = 0; it < PT; it++) acc[it] = bp[o0 + 2*it];

    #pragma unroll
    for (int cb = 0; cb < CSZ; cb += 16) {
        float xr[16];
        #pragma unroll
        for (int cc = 0; cc < 16; cc++) xr[cc] = xs[(cb+cc)*FSZ + f];
        #pragma unroll
        for (int it = 0; it < PT; it++) {
            const float* wr = ws + (o0 + 2*it)*CSZ + cb;
            #pragma unroll
            for (int cc = 0; cc < 16; cc++) acc[it] += xr[cc]*wr[cc];
        }
    }

    const float a = ap[0];
    float s1 = 0.f, s2 = 0.f;
    #pragma unroll
    for (int it = 0; it < PT; it++) {
        float y = acc[it];
        y = y > 0.f ? y : a*y;
        acc[it] = y; s1 += y; s2 += y*y;
    }
    #pragma unroll
    for (int off = 16; off; off >>= 1) {
        s1 += __shfl_xor_sync(0xffffffffu, s1, off);
        s2 += __shfl_xor_sync(0xffffffffu, s2, off);
    }
    if ((tid & 31) == 0) { atomicAdd(&red[0], s1); atomicAdd(&red[1], s2); }
    __syncthreads();

    constexpr float invn = 1.0f/(CSZ*FSZ);
    float mean = red[0]*invn;
    float var = red[1]*invn - mean*mean;
    float rstd = rsqrtf(var + 1e-5f);
    #pragma unroll
    for (int it = 0; it < PT; it++) {
        int o = o0 + 2*it;
        int j = o*FSZ + f;
        size_t gi = (((size_t)b*CSZ + o)*TSZ + t)*FSZ + f;
        out[gi] = (acc[it]-mean)*rstd*gp[j] + bep[j] + x[gi];
    }
}

// ===========================================================================
extern "C" void kernel_launch(void* const* d_in, const int* in_sizes, int n_in,
                              void* d_out, int out_size)
{
    const float* x   = (const float*)d_in[0];
    const float* Wq  = (const float*)d_in[1];
    const float* bq  = (const float*)d_in[2];
    const float* aq  = (const float*)d_in[3];
    const float* gq  = (const float*)d_in[4];
    const float* beq = (const float*)d_in[5];
    const float* Wk  = (const float*)d_in[6];
    const float* bk  = (const float*)d_in[7];
    const float* ak  = (const float*)d_in[8];
    const float* gk  = (const float*)d_in[9];
    const float* bek = (const float*)d_in[10];
    const float* Wv  = (const float*)d_in[11];
    const float* bv  = (const float*)d_in[12];
    const float* av  = (const float*)d_in[13];
    const float* gv  = (const float*)d_in[14];
    const float* bev = (const float*)d_in[15];
    const float* Wp  = (const float*)d_in[16];
    const float* bp  = (const float*)d_in[17];
    const float* ap  = (const float*)d_in[18];
    const float* gp  = (const float*)d_in[19];
    const float* bep = (const float*)d_in[20];
    float* out = (float*)d_out;

    const int SMEM_EW = 12288*(int)sizeof(float);     // 48 KB (qkv/proj)
    const int SMEM_QK = 4*TILE_U32*4;                 // 72 KB
    const int SMEM_PV = 2*TILE_U32*4;                 // 36 KB
    cudaFuncSetAttribute(qkv_kernel,   cudaFuncAttributeMaxDynamicSharedMemorySize, SMEM_EW);
    cudaFuncSetAttribute(proj_kernel,  cudaFuncAttributeMaxDynamicSharedMemorySize, SMEM_EW);
    cudaFuncSetAttribute(gemm_qk_mma,  cudaFuncAttributeMaxDynamicSharedMemorySize, SMEM_QK);
    cudaFuncSetAttribute(gemm_pv_mma,  cudaFuncAttributeMaxDynamicSharedMemorySize, SMEM_PV);

    qkv_kernel<<<BSZ*TSZ, 256, SMEM_EW>>>(x, Wq, bq, aq, gq, beq,
                                          Wk, bk, ak, gk, bek,
                                          Wv, bv, av, gv, bev);
    vtrans_kernel<<<dim3(DV/32, TSZ/32, NB), 256>>>();
    gemm_qk_mma<<<dim3(8, 8, NB), 256, SMEM_QK>>>();
    softmax_kernel<<<NB*TSZ, 256>>>();
    gemm_pv_mma<<<dim3(16, 8, NB), 256, SMEM_PV>>>();
    proj_kernel<<<BSZ*TSZ, 256, SMEM_EW>>>(x, Wp, bp, ap, gp, bep, out);
}

// round 4
// speedup vs baseline: 1.9139x; 1.1603x over previous
#include <cuda_runtime.h>
#include <cstdint>

// Problem constants
#define BSZ 4
#define CSZ 64
#define TSZ 1024
#define FSZ 128
#define HN  4
#define HIDN 4
#define CHN 16
#define NB  (HN*BSZ)      // 16 attention batches
#define DQK (HIDN*FSZ)    // 512
#define DV  (CHN*FSZ)     // 2048

// Scratch (device globals: allocation-free rule)
__device__ float g_q [(size_t)NB*TSZ*DQK];           // [n][t][d]
__device__ float g_k [(size_t)NB*TSZ*DQK];           // [n][t][d]
__device__ float g_v [(size_t)NB*TSZ*DV];            // [n][t][d]
__device__ float g_vt[(size_t)NB*DV*TSZ];            // [n][d][t] (tf32-rounded)
__device__ float g_s [(size_t)NB*TSZ*TSZ];           // [n][t][t']
__device__ float g_ao[(size_t)BSZ*CSZ*TSZ*FSZ];

// ===========================================================================
// mma.sync helpers (portable PTX, works on compute_103 target)
// ===========================================================================
__device__ __forceinline__ uint32_t smem_u32(const void* p) {
    uint32_t a;
    asm("{ .reg .u64 t; cvta.to.shared.u64 t, %1; cvt.u32.u64 %0, t; }" : "=r"(a) : "l"(p));
    return a;
}
__device__ __forceinline__ uint32_t cvt_tf32(float v) {
    uint32_t r;
    asm("cvt.rna.tf32.f32 %0, %1;" : "=r"(r) : "f"(v));
    return r;
}
__device__ __forceinline__ void ldsm4(uint32_t& r0, uint32_t& r1, uint32_t& r2, uint32_t& r3,
                                      uint32_t addr) {
    asm volatile("ldmatrix.sync.aligned.m8n8.x4.shared.b16 {%0,%1,%2,%3}, [%4];"
                 : "=r"(r0), "=r"(r1), "=r"(r2), "=r"(r3) : "r"(addr));
}
__device__ __forceinline__ void mma8(float* d, const uint32_t* a, uint32_t b0, uint32_t b1) {
    asm volatile("mma.sync.aligned.m16n8k8.row.col.f32.tf32.tf32.f32 "
                 "{%0,%1,%2,%3}, {%4,%5,%6,%7}, {%8,%9}, {%0,%1,%2,%3};"
                 : "+f"(d[0]), "+f"(d[1]), "+f"(d[2]), "+f"(d[3])
                 : "r"(a[0]), "r"(a[1]), "r"(a[2]), "r"(a[3]), "r"(b0), "r"(b1));
}

#define LDS_ROW 36              // 32 k-floats + 4 pad (conflict-free ldmatrix)
#define TILE_U32 (128*LDS_ROW)  // one 128x32 tile in smem (u32 units)

// ===========================================================================
// QKV: per-(b,t) block: Y[96,128] = Wall[96,64] @ X[64,128]  (3xTF32)
//   rows 0-15 = Wq(h*4+o), 16-31 = Wk, 32-95 = Wv(h*16+ch)
//   8 warps: 2 m-warps (48 rows) x 4 n-warps (32 cols)
// ===========================================================================
#define QKV_WPITCH 36     // per-chunk W row pitch (32 k + 4)
#define QKV_XPITCH 136    // X row pitch over f (128 + 8)

__global__ void __launch_bounds__(256) qkv_mma(
    const float* __restrict__ x,
    const float* __restrict__ Wq, const float* __restrict__ bq,
    const float* __restrict__ aq, const float* __restrict__ gq, const float* __restrict__ beq,
    const float* __restrict__ Wk, const float* __restrict__ bk,
    const float* __restrict__ ak, const float* __restrict__ gk, const float* __restrict__ bek,
    const float* __restrict__ Wv, const float* __restrict__ bv,
    const float* __restrict__ av, const float* __restrict__ gv, const float* __restrict__ bev)
{
    extern __shared__ uint32_t dynsm[];
    uint32_t* Wsh = dynsm;                      // 96*36
    uint32_t* Wsl = Wsh + 96*QKV_WPITCH;
    uint32_t* Xsh = Wsl + 96*QKV_WPITCH;        // 32*136
    uint32_t* Xsl = Xsh + 32*QKV_XPITCH;
    __shared__ float rowred[96*2];
    __shared__ float stats[12*2];
    __shared__ float biasS[96], alphS[96];

    const int tid = threadIdx.x, lane = tid & 31, warp = tid >> 5;
    const int wm = warp >> 2, wn = warp & 3;
    const int ly = lane >> 2, lx = lane & 3;
    const int b = blockIdx.x >> 10, t = blockIdx.x & 1023;

    if (tid < 192) rowred[tid] = 0.f;
    if (tid < 96) {
        if (tid < 16)      { biasS[tid] = bq[tid];    alphS[tid] = aq[tid>>2]; }
        else if (tid < 32) { biasS[tid] = bk[tid-16]; alphS[tid] = ak[(tid-16)>>2]; }
        else               { biasS[tid] = bv[tid-32]; alphS[tid] = av[(tid-32)>>4]; }
    }

    float acc[3][4][4];
    #pragma unroll
    for (int i = 0; i < 3; i++)
        #pragma unroll
        for (int j = 0; j < 4; j++)
            #pragma unroll
            for (int k = 0; k < 4; k++) acc[i][j][k] = 0.f;

    #pragma unroll
    for (int kcb = 0; kcb < 2; kcb++) {
        const int kc = kcb*32;
        // W chunk: 96 rows x 32 cols
        #pragma unroll
        for (int j = 0; j < 3; j++) {
            int idx = tid + 256*j;              // 0..767
            int row = idx >> 3, c4 = idx & 7;
            const float* src;
            if (row < 16)      src = Wq + row*CSZ;
            else if (row < 32) src = Wk + (row-16)*CSZ;
            else               src = Wv + (row-32)*CSZ;
            float4 w = *(const float4*)(src + kc + c4*4);
            int o = row*QKV_WPITCH + c4*4;
            uint32_t h;
            h = cvt_tf32(w.x); Wsh[o+0] = h; Wsl[o+0] = cvt_tf32(w.x - __uint_as_float(h));
            h = cvt_tf32(w.y); Wsh[o+1] = h; Wsl[o+1] = cvt_tf32(w.y - __uint_as_float(h));
            h = cvt_tf32(w.z); Wsh[o+2] = h; Wsl[o+2] = cvt_tf32(w.z - __uint_as_float(h));
            h = cvt_tf32(w.w); Wsh[o+3] = h; Wsl[o+3] = cvt_tf32(w.w - __uint_as_float(h));
        }
        // X chunk: 32 c-rows x 128 f (natural layout [c][f])
        #pragma unroll
        for (int j = 0; j < 4; j++) {
            int p = tid + 256*j;                // 0..1023
            int f = p & 127, c4 = p >> 7;
            #pragma unroll
            for (int e = 0; e < 4; e++) {
                int c = c4*4 + e;
                float v = x[(((size_t)(b*CSZ + kc + c))*TSZ + t)*FSZ + f];
                uint32_t h = cvt_tf32(v);
                Xsh[c*QKV_XPITCH + f] = h;
                Xsl[c*QKV_XPITCH + f] = cvt_tf32(v - __uint_as_float(h));
            }
        }
        __syncthreads();

        #pragma unroll
        for (int ks = 0; ks < 4; ks++) {
            uint32_t ah[3][4], al[3][4], bh[4][2], bl[4][2];
            #pragma unroll
            for (int im = 0; im < 3; im++) {
                int rb = (wm*48 + im*16 + ly)*QKV_WPITCH + ks*8 + lx;
                ah[im][0] = Wsh[rb];     ah[im][1] = Wsh[rb + 8*QKV_WPITCH];
                ah[im][2] = Wsh[rb + 4]; ah[im][3] = Wsh[rb + 8*QKV_WPITCH + 4];
                al[im][0] = Wsl[rb];     al[im][1] = Wsl[rb + 8*QKV_WPITCH];
                al[im][2] = Wsl[rb + 4]; al[im][3] = Wsl[rb + 8*QKV_WPITCH + 4];
            }
            #pragma unroll
            for (int in = 0; in < 4; in++) {
                int cb = (ks*8 + lx)*QKV_XPITCH + wn*32 + in*8 + ly;
                bh[in][0] = Xsh[cb]; bh[in][1] = Xsh[cb + 4*QKV_XPITCH];
                bl[in][0] = Xsl[cb]; bl[in][1] = Xsl[cb + 4*QKV_XPITCH];
            }
            #pragma unroll
            for (int im = 0; im < 3; im++)
                #pragma unroll
                for (int in = 0; in < 4; in++) {
                    mma8(acc[im][in], ah[im], bh[in][0], bh[in][1]);
                    mma8(acc[im][in], ah[im], bl[in][0], bl[in][1]);
                    mma8(acc[im][in], al[im], bh[in][0], bh[in][1]);
                }
        }
        __syncthreads();
    }

    // ---- bias + PReLU + per-row partial sums ----
    float rs[3][2], rq[3][2];
    #pragma unroll
    for (int im = 0; im < 3; im++) { rs[im][0]=rs[im][1]=0.f; rq[im][0]=rq[im][1]=0.f; }
    #pragma unroll
    for (int im = 0; im < 3; im++)
        #pragma unroll
        for (int hh = 0; hh < 2; hh++) {
            int r = wm*48 + im*16 + ly + hh*8;
            float bi = biasS[r], alp = alphS[r];
            #pragma unroll
            for (int in = 0; in < 4; in++)
                #pragma unroll
                for (int e = 0; e < 2; e++) {
                    float y = acc[im][in][hh*2+e] + bi;
                    y = y > 0.f ? y : alp*y;
                    acc[im][in][hh*2+e] = y;
                    rs[im][hh] += y; rq[im][hh] += y*y;
                }
        }
    #pragma unroll
    for (int im = 0; im < 3; im++)
        #pragma unroll
        for (int hh = 0; hh < 2; hh++) {
            float s = rs[im][hh], q = rq[im][hh];
            s += __shfl_xor_sync(0xffffffffu, s, 1); q += __shfl_xor_sync(0xffffffffu, q, 1);
            s += __shfl_xor_sync(0xffffffffu, s, 2); q += __shfl_xor_sync(0xffffffffu, q, 2);
            if (lx == 0) {
                int r = wm*48 + im*16 + ly + hh*8;
                atomicAdd(&rowred[2*r], s); atomicAdd(&rowred[2*r+1], q);
            }
        }
    __syncthreads();
    if (tid < 12) {
        int st, cnt;
        if (tid < 8) { st = tid*4; cnt = 4; } else { st = 32 + (tid-8)*16; cnt = 16; }
        float s = 0.f, q = 0.f;
        for (int r = st; r < st+cnt; r++) { s += rowred[2*r]; q += rowred[2*r+1]; }
        float inv = 1.f/(cnt*FSZ);
        float mean = s*inv, var = q*inv - mean*mean;
        stats[2*tid] = mean; stats[2*tid+1] = rsqrtf(var + 1e-5f);
    }
    __syncthreads();

    // ---- normalize + store q/k/v ----
    #pragma unroll
    for (int im = 0; im < 3; im++)
        #pragma unroll
        for (int hh = 0; hh < 2; hh++) {
            int r = wm*48 + im*16 + ly + hh*8;
            int grp = (r < 32) ? (r >> 2) : ((r >> 4) + 6);
            float mean = stats[2*grp], rstd = stats[2*grp+1];
            const float* gvec; const float* bevec; float* dst; int jrow;
            if (r < 16) {
                jrow = r; gvec = gq; bevec = beq;
                dst = g_q + (((size_t)((r>>2)*BSZ + b)*TSZ + t)*DQK) + (r&3)*FSZ;
            } else if (r < 32) {
                jrow = r - 16; gvec = gk; bevec = bek;
                dst = g_k + (((size_t)(((r-16)>>2)*BSZ + b)*TSZ + t)*DQK) + ((r-16)&3)*FSZ;
            } else {
                jrow = r - 32; gvec = gv; bevec = bev;
                dst = g_v + (((size_t)(((r-32)>>4)*BSZ + b)*TSZ + t)*DV) + ((r-32)&15)*FSZ;
            }
            #pragma unroll
            for (int in = 0; in < 4; in++) {
                int c = wn*32 + in*8 + lx*2;
                float y0 = (acc[im][in][hh*2+0]-mean)*rstd*gvec[jrow*FSZ+c]   + bevec[jrow*FSZ+c];
                float y1 = (acc[im][in][hh*2+1]-mean)*rstd*gvec[jrow*FSZ+c+1] + bevec[jrow*FSZ+c+1];
                *(float2*)(dst + c) = make_float2(y0, y1);
            }
        }
}

// ===========================================================================
// PROJ: per-(b,t): Y[64,128] = Wp[64,64] @ AO[64,128] (3xTF32) + norm + residual
// ===========================================================================
__global__ void __launch_bounds__(256) proj_mma(
    const float* __restrict__ x, const float* __restrict__ Wp,
    const float* __restrict__ bp, const float* __restrict__ ap,
    const float* __restrict__ gp, const float* __restrict__ bep,
    float* __restrict__ out)
{
    extern __shared__ uint32_t dynsm[];
    uint32_t* Wsh = dynsm;                      // 64*36
    uint32_t* Wsl = Wsh + 64*QKV_WPITCH;
    uint32_t* Xsh = Wsl + 64*QKV_WPITCH;        // 32*136
    uint32_t* Xsl = Xsh + 32*QKV_XPITCH;
    __shared__ float red[2];
    __shared__ float statv[2];

    const int tid = threadIdx.x, lane = tid & 31, warp = tid >> 5;
    const int wm = warp >> 2, wn = warp & 3;
    const int ly = lane >> 2, lx = lane & 3;
    const int b = blockIdx.x >> 10, t = blockIdx.x & 1023;

    if (tid < 2) red[tid] = 0.f;

    float acc[2][4][4];
    #pragma unroll
    for (int i = 0; i < 2; i++)
        #pragma unroll
        for (int j = 0; j < 4; j++)
            #pragma unroll
            for (int k = 0; k < 4; k++) acc[i][j][k] = 0.f;

    #pragma unroll
    for (int kcb = 0; kcb < 2; kcb++) {
        const int kc = kcb*32;
        #pragma unroll
        for (int j = 0; j < 2; j++) {
            int idx = tid + 256*j;              // 0..511
            int row = idx >> 3, c4 = idx & 7;
            float4 w = *(const float4*)(Wp + row*CSZ + kc + c4*4);
            int o = row*QKV_WPITCH + c4*4;
            uint32_t h;
            h = cvt_tf32(w.x); Wsh[o+0] = h; Wsl[o+0] = cvt_tf32(w.x - __uint_as_float(h));
            h = cvt_tf32(w.y); Wsh[o+1] = h; Wsl[o+1] = cvt_tf32(w.y - __uint_as_float(h));
            h = cvt_tf32(w.z); Wsh[o+2] = h; Wsl[o+2] = cvt_tf32(w.z - __uint_as_float(h));
            h = cvt_tf32(w.w); Wsh[o+3] = h; Wsl[o+3] = cvt_tf32(w.w - __uint_as_float(h));
        }
        #pragma unroll
        for (int j = 0; j < 4; j++) {
            int p = tid + 256*j;
            int f = p & 127, c4 = p >> 7;
            #pragma unroll
            for (int e = 0; e < 4; e++) {
                int c = c4*4 + e;
                float v = g_ao[(((size_t)(b*CSZ + kc + c))*TSZ + t)*FSZ + f];
                uint32_t h = cvt_tf32(v);
                Xsh[c*QKV_XPITCH + f] = h;
                Xsl[c*QKV_XPITCH + f] = cvt_tf32(v - __uint_as_float(h));
            }
        }
        __syncthreads();

        #pragma unroll
        for (int ks = 0; ks < 4; ks++) {
            uint32_t ah[2][4], al[2][4], bh[4][2], bl[4][2];
            #pragma unroll
            for (int im = 0; im < 2; im++) {
                int rb = (wm*32 + im*16 + ly)*QKV_WPITCH + ks*8 + lx;
                ah[im][0] = Wsh[rb];     ah[im][1] = Wsh[rb + 8*QKV_WPITCH];
                ah[im][2] = Wsh[rb + 4]; ah[im][3] = Wsh[rb + 8*QKV_WPITCH + 4];
                al[im][0] = Wsl[rb];     al[im][1] = Wsl[rb + 8*QKV_WPITCH];
                al[im][2] = Wsl[rb + 4]; al[im][3] = Wsl[rb + 8*QKV_WPITCH + 4];
            }
            #pragma unroll
            for (int in = 0; in < 4; in++) {
                int cb = (ks*8 + lx)*QKV_XPITCH + wn*32 + in*8 + ly;
                bh[in][0] = Xsh[cb]; bh[in][1] = Xsh[cb + 4*QKV_XPITCH];
                bl[in][0] = Xsl[cb]; bl[in][1] = Xsl[cb + 4*QKV_XPITCH];
            }
            #pragma unroll
            for (int im = 0; im < 2; im++)
                #pragma unroll
                for (int in = 0; in < 4; in++) {
                    mma8(acc[im][in], ah[im], bh[in][0], bh[in][1]);
                    mma8(acc[im][in], ah[im], bl[in][0], bl[in][1]);
                    mma8(acc[im][in], al[im], bh[in][0], bh[in][1]);
                }
        }
        __syncthreads();
    }

    // bias + PReLU + block-wide norm (single group)
    const float alp = ap[0];
    float s1 = 0.f, s2 = 0.f;
    #pragma unroll
    for (int im = 0; im < 2; im++)
        #pragma unroll
        for (int hh = 0; hh < 2; hh++) {
            int r = wm*32 + im*16 + ly + hh*8;
            float bi = bp[r];
            #pragma unroll
            for (int in = 0; in < 4; in++)
                #pragma unroll
                for (int e = 0; e < 2; e++) {
                    float y = acc[im][in][hh*2+e] + bi;
                    y = y > 0.f ? y : alp*y;
                    acc[im][in][hh*2+e] = y;
                    s1 += y; s2 += y*y;
                }
        }
    #pragma unroll
    for (int off = 16; off; off >>= 1) {
        s1 += __shfl_xor_sync(0xffffffffu, s1, off);
        s2 += __shfl_xor_sync(0xffffffffu, s2, off);
    }
    if (lane == 0) { atomicAdd(&red[0], s1); atomicAdd(&red[1], s2); }
    __syncthreads();
    if (tid == 0) {
        const float invn = 1.f/(CSZ*FSZ);
        float mean = red[0]*invn, var = red[1]*invn - mean*mean;
        statv[0] = mean; statv[1] = rsqrtf(var + 1e-5f);
    }
    __syncthreads();
    const float mean = statv[0], rstd = statv[1];

    #pragma unroll
    for (int im = 0; im < 2; im++)
        #pragma unroll
        for (int hh = 0; hh < 2; hh++) {
            int r = wm*32 + im*16 + ly + hh*8;
            size_t rowoff = (((size_t)(b*CSZ + r))*TSZ + t)*FSZ;
            #pragma unroll
            for (int in = 0; in < 4; in++) {
                int c = wn*32 + in*8 + lx*2;
                float2 xr = *(const float2*)(x + rowoff + c);
                float y0 = (acc[im][in][hh*2+0]-mean)*rstd*gp[r*FSZ+c]   + bep[r*FSZ+c]   + xr.x;
                float y1 = (acc[im][in][hh*2+1]-mean)*rstd*gp[r*FSZ+c+1] + bep[r*FSZ+c+1] + xr.y;
                *(float2*)(out + rowoff + c) = make_float2(y0, y1);
            }
        }
}

// ===========================================================================
// GEMM 1: S = scale * Q K^T   (3xTF32 split, NT, 128x128x32 tiles) [unchanged]
// ===========================================================================
__global__ void __launch_bounds__(256, 2) gemm_qk_mma()
{
    extern __shared__ uint32_t smq[];
    uint32_t* Ah = smq;
    uint32_t* Al = smq + TILE_U32;
    uint32_t* Bh = smq + 2*TILE_U32;
    uint32_t* Bl = smq + 3*TILE_U32;

    const int tid = threadIdx.x, lane = tid & 31, warp = tid >> 5;
    const int wm = warp >> 2, wn = warp & 3;
    const int bz = blockIdx.z, m0 = blockIdx.y*128, n0 = blockIdx.x*128;
    const float* A = g_q + ((size_t)bz*TSZ + m0)*DQK;
    const float* B = g_k + ((size_t)bz*TSZ + n0)*DQK;

    float acc[4][4][4];
    #pragma unroll
    for (int i = 0; i < 4; i++)
        #pragma unroll
        for (int j = 0; j < 4; j++)
            #pragma unroll
            for (int k = 0; k < 4; k++) acc[i][j][k] = 0.f;

    const uint32_t sbase = smem_u32(smq);
    const uint32_t pAh = sbase + (((wm*64 + (lane & 15))*LDS_ROW) + (lane >> 4)*4)*4;
    const uint32_t pAl = pAh + TILE_U32*4;
    const uint32_t pBh = sbase + (2*TILE_U32 + (wn*32 + lane)*LDS_ROW)*4;
    const uint32_t pBl = pBh + TILE_U32*4;

    for (int c = 0; c < DQK/32; c++) {
        float4 va[4], vb[4];
        #pragma unroll
        for (int j = 0; j < 4; j++) {
            int idx = tid + 256*j, rr = idx >> 3, qq = idx & 7;
            va[j] = *(const float4*)(A + (size_t)rr*DQK + c*32 + qq*4);
            vb[j] = *(const float4*)(B + (size_t)rr*DQK + c*32 + qq*4);
        }
        __syncthreads();
        #pragma unroll
        for (int j = 0; j < 4; j++) {
            int idx = tid + 256*j, rr = idx >> 3, qq = idx & 7;
            int o = rr*LDS_ROW + qq*4;
            uint4 h, l;
            h.x = cvt_tf32(va[j].x); l.x = cvt_tf32(va[j].x - __uint_as_float(h.x));
            h.y = cvt_tf32(va[j].y); l.y = cvt_tf32(va[j].y - __uint_as_float(h.y));
            h.z = cvt_tf32(va[j].z); l.z = cvt_tf32(va[j].z - __uint_as_float(h.z));
            h.w = cvt_tf32(va[j].w); l.w = cvt_tf32(va[j].w - __uint_as_float(h.w));
            *(uint4*)(Ah + o) = h; *(uint4*)(Al + o) = l;
            h.x = cvt_tf32(vb[j].x); l.x = cvt_tf32(vb[j].x - __uint_as_float(h.x));
            h.y = cvt_tf32(vb[j].y); l.y = cvt_tf32(vb[j].y - __uint_as_float(h.y));
            h.z = cvt_tf32(vb[j].z); l.z = cvt_tf32(vb[j].z - __uint_as_float(h.z));
            h.w = cvt_tf32(vb[j].w); l.w = cvt_tf32(vb[j].w - __uint_as_float(h.w));
            *(uint4*)(Bh + o) = h; *(uint4*)(Bl + o) = l;
        }
        __syncthreads();

        #pragma unroll
        for (int ks = 0; ks < 4; ks++) {
            uint32_t ah[4][4], al[4][4], bh0[4], bh1[4], bl0[4], bl1[4];
            #pragma unroll
            for (int im = 0; im < 4; im++) {
                ldsm4(ah[im][0], ah[im][1], ah[im][2], ah[im][3], pAh + im*(16*LDS_ROW*4) + ks*32);
                ldsm4(al[im][0], al[im][1], al[im][2], al[im][3], pAl + im*(16*LDS_ROW*4) + ks*32);
            }
            ldsm4(bh0[0], bh0[1], bh0[2], bh0[3], pBh + ks*32);
            ldsm4(bh1[0], bh1[1], bh1[2], bh1[3], pBh + ks*32 + 16);
            ldsm4(bl0[0], bl0[1], bl0[2], bl0[3], pBl + ks*32);
            ldsm4(bl1[0], bl1[1], bl1[2], bl1[3], pBl + ks*32 + 16);
            #pragma unroll
            for (int im = 0; im < 4; im++)
                #pragma unroll
                for (int in = 0; in < 4; in++) {
                    mma8(acc[im][in], ah[im], bh0[in], bh1[in]);
                    mma8(acc[im][in], ah[im], bl0[in], bl1[in]);
                    mma8(acc[im][in], al[im], bh0[in], bh1[in]);
                }
        }
    }

    const float scale = 0.0441941738241592f;   // 1/sqrt(512)
    float* Cb = g_s + (size_t)bz*TSZ*TSZ;
    const int mbase = m0 + wm*64, nbase = n0 + wn*32;
    #pragma unroll
    for (int im = 0; im < 4; im++)
        #pragma unroll
        for (int in = 0; in < 4; in++) {
            int rr = mbase + im*16 + (lane >> 2);
            int cc = nbase + in*8 + (lane & 3)*2;
            float2 o0 = make_float2(acc[im][in][0]*scale, acc[im][in][1]*scale);
            float2 o1 = make_float2(acc[im][in][2]*scale, acc[im][in][3]*scale);
            *(float2*)(Cb + (size_t)rr*TSZ + cc)     = o0;
            *(float2*)(Cb + (size_t)(rr+8)*TSZ + cc) = o1;
        }
}

// ===========================================================================
// GEMM 2: O = P V  (single TF32, operands pre-rounded -> pure copy to smem)
// ===========================================================================
__global__ void __launch_bounds__(256, 2) gemm_pv_mma()
{
    extern __shared__ uint32_t smp[];
    uint32_t* As = smp;
    uint32_t* Bs = smp + TILE_U32;

    const int tid = threadIdx.x, lane = tid & 31, warp = tid >> 5;
    const int wm = warp >> 2, wn = warp & 3;
    const int bz = blockIdx.z, m0 = blockIdx.y*128, n0 = blockIdx.x*128;
    const float* A = g_s  + (size_t)bz*TSZ*TSZ + (size_t)m0*TSZ;
    const float* B = g_vt + ((size_t)bz*DV + n0)*TSZ;

    float acc[4][4][4];
    #pragma unroll
    for (int i = 0; i < 4; i++)
        #pragma unroll
        for (int j = 0; j < 4; j++)
            #pragma unroll
            for (int k = 0; k < 4; k++) acc[i][j][k] = 0.f;

    const uint32_t sbase = smem_u32(smp);
    const uint32_t pA = sbase + (((wm*64 + (lane & 15))*LDS_ROW) + (lane >> 4)*4)*4;
    const uint32_t pB = sbase + (TILE_U32 + (wn*32 + lane)*LDS_ROW)*4;

    for (int c = 0; c < TSZ/32; c++) {
        float4 va[4], vb[4];
        #pragma unroll
        for (int j = 0; j < 4; j++) {
            int idx = tid + 256*j, rr = idx >> 3, qq = idx & 7;
            va[j] = *(const float4*)(A + (size_t)rr*TSZ + c*32 + qq*4);
            vb[j] = *(const float4*)(B + (size_t)rr*TSZ + c*32 + qq*4);
        }
        __syncthreads();
        #pragma unroll
        for (int j = 0; j < 4; j++) {
            int idx = tid + 256*j, rr = idx >> 3, qq = idx & 7;
            int o = rr*LDS_ROW + qq*4;
            *(float4*)(As + o) = va[j];
            *(float4*)(Bs + o) = vb[j];
        }
        __syncthreads();

        #pragma unroll
        for (int ks = 0; ks < 4; ks++) {
            uint32_t a[4][4], b0[4], b1[4];
            #pragma unroll
            for (int im = 0; im < 4; im++)
                ldsm4(a[im][0], a[im][1], a[im][2], a[im][3], pA + im*(16*LDS_ROW*4) + ks*32);
            ldsm4(b0[0], b0[1], b0[2], b0[3], pB + ks*32);
            ldsm4(b1[0], b1[1], b1[2], b1[3], pB + ks*32 + 16);
            #pragma unroll
            for (int im = 0; im < 4; im++)
                #pragma unroll
                for (int in = 0; in < 4; in++)
                    mma8(acc[im][in], a[im], b0[in], b1[in]);
        }
    }

    const int h = bz >> 2, bb = bz & 3;
    const int cc_ch = h*CHN + blockIdx.x;
    const int mbase = m0 + wm*64, nbase = wn*32;
    float* Ob = g_ao + ((size_t)(bb*CSZ + cc_ch)*TSZ)*FSZ;
    #pragma unroll
    for (int im = 0; im < 4; im++)
        #pragma unroll
        for (int in = 0; in < 4; in++) {
            int rr = mbase + im*16 + (lane >> 2);
            int ff = nbase + in*8 + (lane & 3)*2;
            float2 o0 = make_float2(acc[im][in][0], acc[im][in][1]);
            float2 o1 = make_float2(acc[im][in][2], acc[im][in][3]);
            *(float2*)(Ob + (size_t)rr*FSZ + ff)     = o0;
            *(float2*)(Ob + (size_t)(rr+8)*FSZ + ff) = o1;
        }
}

// ===========================================================================
// V transpose: g_v [n][t][d] -> g_vt [n][d][t]  (tf32-rounded at write)
// ===========================================================================
__global__ void __launch_bounds__(256) vtrans_kernel()
{
    __shared__ float ts[32][33];
    const int n = blockIdx.z;
    const int d0 = blockIdx.x*32, t0 = blockIdx.y*32;
    const int tx = threadIdx.x & 31, ty = threadIdx.x >> 5;
    const float* src = g_v + (size_t)n*TSZ*DV;
    #pragma unroll
    for (int k = 0; k < 4; k++)
        ts[ty + 8*k][tx] = src[(size_t)(t0 + ty + 8*k)*DV + d0 + tx];
    __syncthreads();
    float* dst = g_vt + (size_t)n*DV*TSZ;
    #pragma unroll
    for (int k = 0; k < 4; k++)
        dst[(size_t)(d0 + ty + 8*k)*TSZ + t0 + tx] = __uint_as_float(cvt_tf32(ts[tx][ty + 8*k]));
}

// ===========================================================================
// Softmax (rows of 1024); writes tf32-rounded P so gemm_pv skips conversion
// ===========================================================================
__global__ void __launch_bounds__(256) softmax_kernel()
{
    float* p = g_s + (size_t)blockIdx.x*TSZ;
    const int tid = threadIdx.x;
    __shared__ float red[256];

    float v0 = p[tid], v1 = p[tid+256], v2 = p[tid+512], v3 = p[tid+768];
    float m = fmaxf(fmaxf(v0,v1), fmaxf(v2,v3));
    red[tid] = m; __syncthreads();
    #pragma unroll
    for (int s = 128; s > 0; s >>= 1) {
        if (tid < s) red[tid] = fmaxf(red[tid], red[tid+s]);
        __syncthreads();
    }
    m = red[0]; __syncthreads();

    v0 = __expf(v0-m); v1 = __expf(v1-m); v2 = __expf(v2-m); v3 = __expf(v3-m);
    red[tid] = v0+v1+v2+v3; __syncthreads();
    #pragma unroll
    for (int s = 128; s > 0; s >>= 1) {
        if (tid < s) red[tid] += red[tid+s];
        __syncthreads();
    }
    float inv = 1.0f/red[0];
    p[tid]     = __uint_as_float(cvt_tf32(v0*inv));
    p[tid+256] = __uint_as_float(cvt_tf32(v1*inv));
    p[tid+512] = __uint_as_float(cvt_tf32(v2*inv));
    p[tid+768] = __uint_as_float(cvt_tf32(v3*inv));
}

// ===========================================================================
extern "C" void kernel_launch(void* const* d_in, const int* in_sizes, int n_in,
                              void* d_out, int out_size)
{
    const float* x   = (const float*)d_in[0];
    const float* Wq  = (const float*)d_in[1];
    const float* bq  = (const float*)d_in[2];
    const float* aq  = (const float*)d_in[3];
    const float* gq  = (const float*)d_in[4];
    const float* beq = (const float*)d_in[5];
    const float* Wk  = (const float*)d_in[6];
    const float* bk  = (const float*)d_in[7];
    const float* ak  = (const float*)d_in[8];
    const float* gk  = (const float*)d_in[9];
    const float* bek = (const float*)d_in[10];
    const float* Wv  = (const float*)d_in[11];
    const float* bv  = (const float*)d_in[12];
    const float* av  = (const float*)d_in[13];
    const float* gv  = (const float*)d_in[14];
    const float* bev = (const float*)d_in[15];
    const float* Wp  = (const float*)d_in[16];
    const float* bp  = (const float*)d_in[17];
    const float* ap  = (const float*)d_in[18];
    const float* gp  = (const float*)d_in[19];
    const float* bep = (const float*)d_in[20];
    float* out = (float*)d_out;

    const int SMEM_QKV  = (2*96*QKV_WPITCH + 2*32*QKV_XPITCH)*4;   // ~62.5 KB
    const int SMEM_PROJ = (2*64*QKV_WPITCH + 2*32*QKV_XPITCH)*4;   // ~53 KB
    const int SMEM_QK   = 4*TILE_U32*4;                            // 72 KB
    const int SMEM_PV   = 2*TILE_U32*4;                            // 36 KB
    cudaFuncSetAttribute(qkv_mma,     cudaFuncAttributeMaxDynamicSharedMemorySize, SMEM_QKV);
    cudaFuncSetAttribute(proj_mma,    cudaFuncAttributeMaxDynamicSharedMemorySize, SMEM_PROJ);
    cudaFuncSetAttribute(gemm_qk_mma, cudaFuncAttributeMaxDynamicSharedMemorySize, SMEM_QK);
    cudaFuncSetAttribute(gemm_pv_mma, cudaFuncAttributeMaxDynamicSharedMemorySize, SMEM_PV);

    qkv_mma<<<BSZ*TSZ, 256, SMEM_QKV>>>(x, Wq, bq, aq, gq, beq,
                                        Wk, bk, ak, gk, bek,
                                        Wv, bv, av, gv, bev);
    vtrans_kernel<<<dim3(DV/32, TSZ/32, NB), 256>>>();
    gemm_qk_mma<<<dim3(8, 8, NB), 256, SMEM_QK>>>();
    softmax_kernel<<<NB*TSZ, 256>>>();
    gemm_pv_mma<<<dim3(16, 8, NB), 256, SMEM_PV>>>();
    proj_mma<<<BSZ*TSZ, 256, SMEM_PROJ>>>(x, Wp, bp, ap, gp, bep, out);
}